// round 8
// baseline (speedup 1.0000x reference)
#include <cuda_runtime.h>
#include <cstdint>

// InnerProduct_541165879452
// lp[r,p] = sum_f w[p,f]^2 * sum_e x[r,f,e]^2
// x: [32768, 64, 16] f32 (row = 4 KB), w: [10,64] f32, out: [R,10] f32.
//
// TMA-style bulk-copy pipeline: persistent CTAs, cp.async.bulk streams 32 KB
// tiles (8 rows) into double-buffered smem behind mbarriers; 8 consumer warps
// per CTA do the square+reduce from smem. Removes the per-warp LDG path that
// plateaued every previous variant at ~5 TB/s.

#define P_DIM 10
#define F_DIM 64
#define ROW_FLOATS 1024
#define ROWS_PER_TILE 8
#define TILE_FLOATS (ROWS_PER_TILE * ROW_FLOATS)        // 8192
#define TILE_BYTES (TILE_FLOATS * 4)                    // 32768
#define STAGES 2
#define THREADS 256
#define NUM_CTAS 304
#define SMEM_BYTES (STAGES * TILE_BYTES + 64)           // bufs + 4 mbarriers

__device__ __forceinline__ uint32_t smem_u32(const void* p) {
    return (uint32_t)__cvta_generic_to_shared(p);
}
__device__ __forceinline__ void mbar_init(uint32_t mbar, uint32_t count) {
    asm volatile("mbarrier.init.shared.b64 [%0], %1;" :: "r"(mbar), "r"(count) : "memory");
}
__device__ __forceinline__ void mbar_expect_tx(uint32_t mbar, uint32_t bytes) {
    asm volatile("mbarrier.arrive.expect_tx.shared.b64 _, [%0], %1;"
                 :: "r"(mbar), "r"(bytes) : "memory");
}
// Arrive with a dummy data dependency: forces all smem loads feeding `dep`
// to have completed before the buffer is marked empty.
__device__ __forceinline__ void mbar_arrive_dep(uint32_t mbar, uint32_t dep) {
    asm volatile("mbarrier.arrive.shared.b64 _, [%0];"
                 :: "r"(mbar), "r"(dep) : "memory");
}
__device__ __forceinline__ void mbar_wait(uint32_t mbar, uint32_t parity) {
    asm volatile(
        "{\n\t"
        ".reg .pred P;\n\t"
        "WAIT_%=:\n\t"
        "mbarrier.try_wait.parity.acquire.cta.shared::cta.b64 P, [%0], %1, 0x989680;\n\t"
        "@P bra.uni DONE_%=;\n\t"
        "bra.uni WAIT_%=;\n\t"
        "DONE_%=:\n\t"
        "}"
        :: "r"(mbar), "r"(parity) : "memory");
}
__device__ __forceinline__ void bulk_copy(uint32_t dst_smem, const void* src,
                                          uint32_t bytes, uint32_t mbar) {
    asm volatile(
        "cp.async.bulk.shared::cluster.global.mbarrier::complete_tx::bytes "
        "[%0], [%1], %2, [%3];"
        :: "r"(dst_smem), "l"(src), "r"(bytes), "r"(mbar) : "memory");
}

extern __shared__ __align__(128) unsigned char smem_raw[];

__global__ void __launch_bounds__(THREADS, 2)
ip_kernel(const float* __restrict__ x,
          const float* __restrict__ w,
          float* __restrict__ out,
          int R)
{
    float*    buf  = reinterpret_cast<float*>(smem_raw);
    uint64_t* bars = reinterpret_cast<uint64_t*>(smem_raw + STAGES * TILE_BYTES);
    // bars[0..1] = full, bars[2..3] = empty

    const int tid  = threadIdx.x;
    const int lane = tid & 31;
    const int wid  = tid >> 5;            // 0..7 : consumer row within tile

    uint32_t full_b[STAGES], empty_b[STAGES];
#pragma unroll
    for (int s = 0; s < STAGES; s++) {
        full_b[s]  = smem_u32(&bars[s]);
        empty_b[s] = smem_u32(&bars[STAGES + s]);
    }

    if (tid == 0) {
#pragma unroll
        for (int s = 0; s < STAGES; s++) {
            mbar_init(full_b[s], 1);          // one expect_tx arrival per fill
            mbar_init(empty_b[s], THREADS);   // all threads release the buffer
        }
    }
    __syncthreads();

    // Per-lane squared weights (R1 mapping): lane owns f_a = 16q+c, f_b = f_a+8.
    const int q = lane & 3;
    const int c = lane >> 2;
    const int f_a = 16 * q + c;
    const int f_b = f_a + 8;
    float wa[P_DIM], wb[P_DIM];
#pragma unroll
    for (int p = 0; p < P_DIM; p++) {
        float va = __ldg(&w[p * F_DIM + f_a]);
        float vb = __ldg(&w[p * F_DIM + f_b]);
        wa[p] = va * va;
        wb[p] = vb * vb;
    }

    const int nTiles = R / ROWS_PER_TILE;                        // 4096
    const int n = (nTiles - (int)blockIdx.x + (int)gridDim.x - 1) / (int)gridDim.x;

    // Prologue: fill both stages.
    if (tid == 0) {
#pragma unroll
        for (int s = 0; s < STAGES; s++) {
            if (s < n) {
                long tile = (long)blockIdx.x + (long)s * gridDim.x;
                mbar_expect_tx(full_b[s], TILE_BYTES);
                bulk_copy(smem_u32(buf + (size_t)s * TILE_FLOATS),
                          x + tile * TILE_FLOATS, TILE_BYTES, full_b[s]);
            }
        }
    }

    for (int k = 0; k < n; k++) {
        const int s = k & 1;
        const uint32_t parity = (uint32_t)(k >> 1) & 1u;   // j-th use of stage s

        mbar_wait(full_b[s], parity);

        const long tile = (long)blockIdx.x + (long)k * gridDim.x;
        const float4* rp = reinterpret_cast<const float4*>(
            buf + (size_t)s * TILE_FLOATS + (size_t)wid * ROW_FLOATS);

        // 8 LDS.128 per lane, phase-conflict-free (consecutive lanes 16B apart).
        float4 v[8];
#pragma unroll
        for (int i = 0; i < 8; i++) v[i] = rp[i * 32 + lane];

        float sq[8];
#pragma unroll
        for (int i = 0; i < 8; i++) {
            float t = v[i].x * v[i].x;
            t = fmaf(v[i].y, v[i].y, t);
            t = fmaf(v[i].z, v[i].z, t);
            sq[i] = fmaf(v[i].w, v[i].w, t);
        }

        // Quad reduce: lanes {4c..4c+3} share f for every i.
#pragma unroll
        for (int i = 0; i < 8; i++) {
            sq[i] += __shfl_xor_sync(0xffffffffu, sq[i], 1);
            sq[i] += __shfl_xor_sync(0xffffffffu, sq[i], 2);
        }

        // Checksum over all partials -> data-dependent empty arrival.
        float chk = sq[0] + sq[1] + sq[2] + sq[3] + sq[4] + sq[5] + sq[6] + sq[7];
        mbar_arrive_dep(empty_b[s], __float_as_uint(chk));

        // Producer refill for tile k+2 (overlaps with the reduce below).
        if (tid == 0 && k + STAGES < n) {
            mbar_wait(empty_b[s], parity);
            long t2 = (long)blockIdx.x + (long)(k + STAGES) * gridDim.x;
            mbar_expect_tx(full_b[s], TILE_BYTES);
            bulk_copy(smem_u32(buf + (size_t)s * TILE_FLOATS),
                      x + t2 * TILE_FLOATS, TILE_BYTES, full_b[s]);
        }

        // Static select of this lane's two owned xsq values.
        float xa = (q == 0) ? sq[0] : (q == 1) ? sq[2] : (q == 2) ? sq[4] : sq[6];
        float xb = (q == 0) ? sq[1] : (q == 1) ? sq[3] : (q == 2) ? sq[5] : sq[7];

        float acc[P_DIM];
#pragma unroll
        for (int p = 0; p < P_DIM; p++)
            acc[p] = fmaf(xa, wa[p], xb * wb[p]);

        // Split butterfly: xor16 on 10, then halves carry 5 each.
#pragma unroll
        for (int p = 0; p < P_DIM; p++)
            acc[p] += __shfl_xor_sync(0xffffffffu, acc[p], 16);

        const bool hi = (lane & 16) != 0;
        float a2[5];
#pragma unroll
        for (int j = 0; j < 5; j++)
            a2[j] = hi ? acc[j + 5] : acc[j];

#pragma unroll
        for (int off = 8; off >= 1; off >>= 1) {
#pragma unroll
            for (int j = 0; j < 5; j++)
                a2[j] += __shfl_xor_sync(0xffffffffu, a2[j], off);
        }

        const long row = tile * ROWS_PER_TILE + wid;
        float* orow = out + row * P_DIM;
        if (lane == 0) {
#pragma unroll
            for (int j = 0; j < 5; j++) orow[j] = a2[j];
        } else if (lane == 16) {
#pragma unroll
            for (int j = 0; j < 5; j++) orow[5 + j] = a2[j];
        }
    }
}

extern "C" void kernel_launch(void* const* d_in, const int* in_sizes, int n_in,
                              void* d_out, int out_size)
{
    const float* x = (const float*)d_in[0];
    const float* w = (const float*)d_in[1];
    float* out = (float*)d_out;

    const int R = in_sizes[0] / ROW_FLOATS;   // 32768

    static int attr_done = 0;
    if (!attr_done) {
        cudaFuncSetAttribute(ip_kernel,
                             cudaFuncAttributeMaxDynamicSharedMemorySize,
                             SMEM_BYTES);
        attr_done = 1;
    }

    ip_kernel<<<NUM_CTAS, THREADS, SMEM_BYTES>>>(x, w, out, R);
}

// round 10
// speedup vs baseline: 2.2406x; 2.2406x over previous
#include <cuda_runtime.h>
#include <cstdint>

// InnerProduct_541165879452
// lp[r,p] = sum_f w[p,f]^2 * sum_e x[r,f,e]^2
// x: [32768, 64, 16] f32 (row = 4 KB), w: [10,64] f32, out: [R,10] f32.
//
// R1's proven memory pattern (one warp per row, 8 coalesced LDG.128,
// quad + split-butterfly shuffle reduce) wrapped in a persistent grid:
// 912 CTAs (6/SM exactly), atomic 16-row tile scheduler (no wave
// quantization, no static imbalance), weights loaded+squared once per warp.

#define P_DIM 10
#define F_DIM 64
#define ROW_FLOATS 1024
#define THREADS 256
#define NUM_CTAS 912                 // 6 per SM on 152 SMs, one exact wave
#define ROWS_PER_TILE 16             // 2 rows per warp per grab

__device__ unsigned int g_tile_ctr;

__global__ void reset_kernel() { g_tile_ctr = 0; }

__global__ __launch_bounds__(THREADS, 6)
void ip_kernel(const float* __restrict__ x,
               const float* __restrict__ w,
               float* __restrict__ out,
               int R)
{
    __shared__ int s_tile;

    const int tid  = threadIdx.x;
    const int lane = tid & 31;
    const int wid  = tid >> 5;           // 0..7

    // Lane feature ownership (R1 mapping): quarters of f = 8i + c live on
    // lanes 4c..4c+3; lane owns f_a = 16q + c and f_b = f_a + 8.
    const int q = lane & 3;
    const int c = lane >> 2;
    const int f_a = 16 * q + c;
    const int f_b = f_a + 8;

    // Squared weights: once per warp, amortized over ~7 rows.
    float wa[P_DIM], wb[P_DIM];
#pragma unroll
    for (int p = 0; p < P_DIM; p++) {
        float va = __ldg(&w[p * F_DIM + f_a]);
        float vb = __ldg(&w[p * F_DIM + f_b]);
        wa[p] = va * va;
        wb[p] = vb * vb;
    }

    const int nTiles = (R + ROWS_PER_TILE - 1) / ROWS_PER_TILE;   // 2048

    for (;;) {
        if (tid == 0) s_tile = (int)atomicAdd(&g_tile_ctr, 1u);
        __syncthreads();
        const int tile = s_tile;
        __syncthreads();                 // s_tile consumed before next overwrite
        if (tile >= nTiles) break;

#pragma unroll
        for (int rr = 0; rr < 2; rr++) {
            const int row = tile * ROWS_PER_TILE + wid * 2 + rr;
            if (row >= R) continue;

            const float4* __restrict__ xr =
                reinterpret_cast<const float4*>(x + (size_t)row * ROW_FLOATS);

            // 8 coalesced LDG.128: lane l reads float4 #(i*32 + l).
            float s[8];
#pragma unroll
            for (int i = 0; i < 8; i++) {
                float4 v = xr[i * 32 + lane];
                float t = v.x * v.x;
                t = fmaf(v.y, v.y, t);
                t = fmaf(v.z, v.z, t);
                s[i] = fmaf(v.w, v.w, t);
            }

            // Quad reduce: lanes {4c..4c+3} share f for every i.
#pragma unroll
            for (int i = 0; i < 8; i++) {
                s[i] += __shfl_xor_sync(0xffffffffu, s[i], 1);
                s[i] += __shfl_xor_sync(0xffffffffu, s[i], 2);
            }

            // Static select of this lane's two owned xsq values.
            float xa = (q == 0) ? s[0] : (q == 1) ? s[2] : (q == 2) ? s[4] : s[6];
            float xb = (q == 0) ? s[1] : (q == 1) ? s[3] : (q == 2) ? s[5] : s[7];

            float acc[P_DIM];
#pragma unroll
            for (int p = 0; p < P_DIM; p++)
                acc[p] = fmaf(xa, wa[p], xb * wb[p]);

            // Split butterfly: xor16 on 10 regs, then halves carry 5 each.
#pragma unroll
            for (int p = 0; p < P_DIM; p++)
                acc[p] += __shfl_xor_sync(0xffffffffu, acc[p], 16);

            const bool hi = (lane & 16) != 0;
            float a2[5];
#pragma unroll
            for (int j = 0; j < 5; j++)
                a2[j] = hi ? acc[j + 5] : acc[j];

#pragma unroll
            for (int off = 8; off >= 1; off >>= 1) {
#pragma unroll
                for (int j = 0; j < 5; j++)
                    a2[j] += __shfl_xor_sync(0xffffffffu, a2[j], off);
            }

            // lanes 0..15 hold p0..4, lanes 16..31 hold p5..9.
            float* orow = out + (size_t)row * P_DIM;
            if (lane == 0) {
#pragma unroll
                for (int j = 0; j < 5; j++) orow[j] = a2[j];
            } else if (lane == 16) {
#pragma unroll
                for (int j = 0; j < 5; j++) orow[5 + j] = a2[j];
            }
        }
    }
}

extern "C" void kernel_launch(void* const* d_in, const int* in_sizes, int n_in,
                              void* d_out, int out_size)
{
    const float* x = (const float*)d_in[0];
    const float* w = (const float*)d_in[1];
    float* out = (float*)d_out;

    const int R = in_sizes[0] / ROW_FLOATS;   // 32768

    reset_kernel<<<1, 1>>>();
    ip_kernel<<<NUM_CTAS, THREADS>>>(x, w, out, R);
}

// round 12
// speedup vs baseline: 2.6851x; 1.1984x over previous
#include <cuda_runtime.h>
#include <cuda_bf16.h>

// InnerProduct_541165879452
// lp[r,p] = sum_f w[p,f]^2 * sum_e x[r,f,e]^2
// x: [32768, 64, 16] f32 (row = 4 KB), w: [10,64] f32, out: [R,10] f32.
//
// R1 (best so far, 28.8us / 5.05 TB/s) with two minimal deltas:
//  - split-butterfly warp reduce: 46 SHFL/row instead of 66
//  - row loads issued before weight loads
// Structure otherwise identical: one-shot grid, one warp per row,
// 8 front-batched coalesced LDG.128, exit.

#define F_DIM 64
#define P_DIM 10
#define ROW_FLOATS 1024
#define WARPS_PER_BLOCK 8

__global__ __launch_bounds__(32 * WARPS_PER_BLOCK)
void ip_kernel(const float* __restrict__ x,
               const float* __restrict__ w,
               float* __restrict__ out,
               int R)
{
    const int wid  = threadIdx.x >> 5;
    const int lane = threadIdx.x & 31;
    const int row  = blockIdx.x * WARPS_PER_BLOCK + wid;
    if (row >= R) return;

    const int c = lane >> 2;   // 0..7 : f-slot within an i-group
    const int q = lane & 3;    // 0..3 : which i-pair this lane owns
    const int f_a = 16 * q + c;
    const int f_b = f_a + 8;

    // ---- Row loads FIRST: 8 coalesced LDG.128, lane l reads float4 #(i*32+l).
    const float4* __restrict__ xr =
        reinterpret_cast<const float4*>(x + (size_t)row * ROW_FLOATS);

    float4 v[8];
#pragma unroll
    for (int i = 0; i < 8; i++) v[i] = xr[i * 32 + lane];

    // ---- Weight loads second (L1-resident after the first warp touches them).
    float wa[P_DIM], wb[P_DIM];
#pragma unroll
    for (int p = 0; p < P_DIM; p++) {
        float va = __ldg(&w[p * F_DIM + f_a]);
        float vb = __ldg(&w[p * F_DIM + f_b]);
        wa[p] = va * va;
        wb[p] = vb * vb;
    }

    // Per-quarter sum of squares.
    float s[8];
#pragma unroll
    for (int i = 0; i < 8; i++) {
        float t = v[i].x * v[i].x;
        t = fmaf(v[i].y, v[i].y, t);
        t = fmaf(v[i].z, v[i].z, t);
        s[i] = fmaf(v[i].w, v[i].w, t);
    }

    // Quad reduce: lanes {4c..4c+3} share f for every i.
#pragma unroll
    for (int i = 0; i < 8; i++) {
        s[i] += __shfl_xor_sync(0xffffffffu, s[i], 1);
        s[i] += __shfl_xor_sync(0xffffffffu, s[i], 2);
    }

    // Static select of this lane's two owned xsq values (f_a, f_b).
    float xa = (q == 0) ? s[0] : (q == 1) ? s[2] : (q == 2) ? s[4] : s[6];
    float xb = (q == 0) ? s[1] : (q == 1) ? s[3] : (q == 2) ? s[5] : s[7];

    float acc[P_DIM];
#pragma unroll
    for (int p = 0; p < P_DIM; p++)
        acc[p] = fmaf(xa, wa[p], xb * wb[p]);

    // Split butterfly: level xor16 on all 10, then halves carry 5 each.
#pragma unroll
    for (int p = 0; p < P_DIM; p++)
        acc[p] += __shfl_xor_sync(0xffffffffu, acc[p], 16);

    const bool hi = (lane & 16) != 0;
    float a2[5];
#pragma unroll
    for (int j = 0; j < 5; j++)
        a2[j] = hi ? acc[j + 5] : acc[j];

#pragma unroll
    for (int off = 8; off >= 1; off >>= 1) {
#pragma unroll
        for (int j = 0; j < 5; j++)
            a2[j] += __shfl_xor_sync(0xffffffffu, a2[j], off);
    }

    // lanes 0..15 all hold p0..4; lanes 16..31 hold p5..9.
    float* orow = out + (size_t)row * P_DIM;
    if (lane == 0) {
#pragma unroll
        for (int j = 0; j < 5; j++) orow[j] = a2[j];
    } else if (lane == 16) {
#pragma unroll
        for (int j = 0; j < 5; j++) orow[5 + j] = a2[j];
    }
}

extern "C" void kernel_launch(void* const* d_in, const int* in_sizes, int n_in,
                              void* d_out, int out_size)
{
    const float* x = (const float*)d_in[0];
    const float* w = (const float*)d_in[1];
    float* out = (float*)d_out;

    const int R = in_sizes[0] / ROW_FLOATS;                          // 32768
    const int blocks = (R + WARPS_PER_BLOCK - 1) / WARPS_PER_BLOCK;  // 4096

    ip_kernel<<<blocks, 32 * WARPS_PER_BLOCK>>>(x, w, out, R);
}

// round 13
// speedup vs baseline: 2.7228x; 1.0140x over previous
#include <cuda_runtime.h>
#include <cuda_bf16.h>

// InnerProduct_541165879452
// lp[r,p] = sum_f w[p,f]^2 * sum_e x[r,f,e]^2
// x: [32768, 64, 16] f32 (row = 4 KB), w: [10,64] f32, out: [R,10] f32.
//
// R12 (best, 27.7us / 5.29 TB/s) + weight amortization: each warp processes
// TWO consecutive rows sequentially with the same squared-weight registers,
// halving the per-row L1 wavefront cost of the divergent weight loads
// (which cost more L1 throughput than the 4KB row itself). Per-row body is
// byte-identical to R12. No cross-row ILP -> no R5-style register blowup.

#define F_DIM 64
#define P_DIM 10
#define ROW_FLOATS 1024
#define WARPS_PER_BLOCK 8
#define ROWS_PER_WARP 2

__global__ __launch_bounds__(32 * WARPS_PER_BLOCK, 5)
void ip_kernel(const float* __restrict__ x,
               const float* __restrict__ w,
               float* __restrict__ out,
               int R)
{
    const int wid  = threadIdx.x >> 5;
    const int lane = threadIdx.x & 31;
    const int row0 = (blockIdx.x * WARPS_PER_BLOCK + wid) * ROWS_PER_WARP;
    if (row0 >= R) return;

    const int c = lane >> 2;   // 0..7 : f-slot within an i-group
    const int q = lane & 3;    // 0..3 : which i-pair this lane owns
    const int f_a = 16 * q + c;
    const int f_b = f_a + 8;

    // Squared weights: loaded ONCE, reused for both rows.
    float wa[P_DIM], wb[P_DIM];
#pragma unroll
    for (int p = 0; p < P_DIM; p++) {
        float va = __ldg(&w[p * F_DIM + f_a]);
        float vb = __ldg(&w[p * F_DIM + f_b]);
        wa[p] = va * va;
        wb[p] = vb * vb;
    }

#pragma unroll
    for (int rr = 0; rr < ROWS_PER_WARP; rr++) {
        const int row = row0 + rr;
        if (row >= R) break;

        const float4* __restrict__ xr =
            reinterpret_cast<const float4*>(x + (size_t)row * ROW_FLOATS);

        // 8 coalesced LDG.128: lane l reads float4 #(i*32 + l).
        float4 v[8];
#pragma unroll
        for (int i = 0; i < 8; i++) v[i] = xr[i * 32 + lane];

        // Per-quarter sum of squares.
        float s[8];
#pragma unroll
        for (int i = 0; i < 8; i++) {
            float t = v[i].x * v[i].x;
            t = fmaf(v[i].y, v[i].y, t);
            t = fmaf(v[i].z, v[i].z, t);
            s[i] = fmaf(v[i].w, v[i].w, t);
        }

        // Quad reduce: lanes {4c..4c+3} share f for every i.
#pragma unroll
        for (int i = 0; i < 8; i++) {
            s[i] += __shfl_xor_sync(0xffffffffu, s[i], 1);
            s[i] += __shfl_xor_sync(0xffffffffu, s[i], 2);
        }

        // Static select of this lane's two owned xsq values (f_a, f_b).
        float xa = (q == 0) ? s[0] : (q == 1) ? s[2] : (q == 2) ? s[4] : s[6];
        float xb = (q == 0) ? s[1] : (q == 1) ? s[3] : (q == 2) ? s[5] : s[7];

        float acc[P_DIM];
#pragma unroll
        for (int p = 0; p < P_DIM; p++)
            acc[p] = fmaf(xa, wa[p], xb * wb[p]);

        // Split butterfly: xor16 on all 10, then halves carry 5 each.
#pragma unroll
        for (int p = 0; p < P_DIM; p++)
            acc[p] += __shfl_xor_sync(0xffffffffu, acc[p], 16);

        const bool hi = (lane & 16) != 0;
        float a2[5];
#pragma unroll
        for (int j = 0; j < 5; j++)
            a2[j] = hi ? acc[j + 5] : acc[j];

#pragma unroll
        for (int off = 8; off >= 1; off >>= 1) {
#pragma unroll
            for (int j = 0; j < 5; j++)
                a2[j] += __shfl_xor_sync(0xffffffffu, a2[j], off);
        }

        // lanes 0..15 all hold p0..4; lanes 16..31 hold p5..9.
        float* orow = out + (size_t)row * P_DIM;
        if (lane == 0) {
#pragma unroll
            for (int j = 0; j < 5; j++) orow[j] = a2[j];
        } else if (lane == 16) {
#pragma unroll
            for (int j = 0; j < 5; j++) orow[5 + j] = a2[j];
        }
    }
}

extern "C" void kernel_launch(void* const* d_in, const int* in_sizes, int n_in,
                              void* d_out, int out_size)
{
    const float* x = (const float*)d_in[0];
    const float* w = (const float*)d_in[1];
    float* out = (float*)d_out;

    const int R = in_sizes[0] / ROW_FLOATS;   // 32768
    const int rows_per_block = WARPS_PER_BLOCK * ROWS_PER_WARP;   // 16
    const int blocks = (R + rows_per_block - 1) / rows_per_block; // 2048

    ip_kernel<<<blocks, 32 * WARPS_PER_BLOCK>>>(x, w, out, R);
}